// round 15
// baseline (speedup 1.0000x reference)
#include <cuda_runtime.h>
#include <cuda_bf16.h>
#include <cuda_fp8.h>
#include <stdint.h>
#include <math.h>

#define NN 4096
#define CC 64
#define HH 128
#define NBS 48
#define OUT_ELEMS (48ULL * 4096ULL * 128ULL)
#define A_ELEMS   (4096ULL * 4096ULL)

// quantization scales (folded out in epilogue): A*16, z*64 -> acc/1024
#define SA 16.0f
#define SZ 64.0f
#define INV_SASZ (1.0f / 1024.0f)

__device__ float g_d[NN];                                   // rsqrt(rowsum(A)+1)
__device__ float g_xemb[(size_t)NBS * NN * HH];             // E fp32 [bs][k][h]
__device__ uint8_t g_a8[A_ELEMS];                           // e4m3(A*16)      (16 MB)
__device__ uint8_t g_e8t[(size_t)NBS * HH * NN];            // e4m3(64*d_k*E), [bs][h][k] (24 MB)

// ---------------------------------------------------------------------------
__device__ __forceinline__ uint32_t smem_u32(const void* p) {
    uint32_t a;
    asm("{ .reg .u64 t; cvta.to.shared.u64 t, %1; cvt.u32.u64 %0, t; }" : "=r"(a) : "l"(p));
    return a;
}
#define LDSM_X4(r, addr) \
    asm volatile("ldmatrix.sync.aligned.m8n8.x4.shared.b16 {%0,%1,%2,%3}, [%4];" \
        : "=r"((r)[0]), "=r"((r)[1]), "=r"((r)[2]), "=r"((r)[3]) : "r"(addr))
__device__ __forceinline__ void mma_fp8(float* c, const uint32_t* a, uint32_t b0, uint32_t b1) {
    asm volatile("mma.sync.aligned.m16n8k32.row.col.f32.e4m3.e4m3.f32 "
                 "{%0,%1,%2,%3}, {%4,%5,%6,%7}, {%8,%9}, {%0,%1,%2,%3};"
                 : "+f"(c[0]), "+f"(c[1]), "+f"(c[2]), "+f"(c[3])
                 : "r"(a[0]), "r"(a[1]), "r"(a[2]), "r"(a[3]), "r"(b0), "r"(b1));
}
#define CP_ASYNC16(saddr, gaddr) \
    asm volatile("cp.async.cg.shared.global [%0], [%1], 16;" :: "r"(saddr), "l"(gaddr))
#define CP_COMMIT() asm volatile("cp.async.commit_group;" ::: "memory")
#define CP_WAIT1()  asm volatile("cp.async.wait_group 1;" ::: "memory")
#define CP_WAIT0()  asm volatile("cp.async.wait_group 0;" ::: "memory")

__device__ __forceinline__ uint32_t pack_fp8x4(float a, float b, float c, float d) {
    __nv_fp8x2_storage_t lo = __nv_cvt_float2_to_fp8x2(make_float2(a, b), __NV_SATFINITE, __NV_E4M3);
    __nv_fp8x2_storage_t hi = __nv_cvt_float2_to_fp8x2(make_float2(c, d), __NV_SATFINITE, __NV_E4M3);
    return (uint32_t)lo | ((uint32_t)hi << 16);
}

// ---------------------------------------------------------------------------
// Kernel 1 (fused): one pass over A -> rowsum/d, e4m3(A*16), fp32 passthrough.
// ---------------------------------------------------------------------------
__global__ void __launch_bounds__(256) rowpass_kernel(const float* __restrict__ A,
                                                      float* __restrict__ outA) {
    int row = blockIdx.x;
    const float4* a4 = (const float4*)(A + (size_t)row * NN);
    float4* o4 = (float4*)(outA + (size_t)row * NN);
    uint32_t* q4 = (uint32_t*)(g_a8 + (size_t)row * NN);
    float s = 0.f;
    #pragma unroll
    for (int j = 0; j < 4; j++) {
        int idx = threadIdx.x + 256 * j;
        float4 v = a4[idx];
        o4[idx] = v;
        q4[idx] = pack_fp8x4(v.x * SA, v.y * SA, v.z * SA, v.w * SA);
        s += v.x + v.y + v.z + v.w;
    }
    #pragma unroll
    for (int o = 16; o > 0; o >>= 1) s += __shfl_down_sync(0xffffffffu, s, o);
    __shared__ float red[8];
    if ((threadIdx.x & 31) == 0) red[threadIdx.x >> 5] = s;
    __syncthreads();
    if (threadIdx.x == 0) {
        float t = 0.f;
        #pragma unroll
        for (int w = 0; w < 8; w++) t += red[w];
        g_d[row] = rsqrtf(t + 1.0f);
    }
}

// ---------------------------------------------------------------------------
// Kernel 2: emb. E fp32 [bs][k][h] and e4m3(64*d_k*E) -> [bs][h][k].
// ---------------------------------------------------------------------------
__global__ void __launch_bounds__(256) emb_kernel(const float* __restrict__ x,
                                                  const float* __restrict__ W) {
    __shared__ float Wt[CC][132];     // W^T padded (33792 B)
    __shared__ float xs[32][CC];      // 32 rows of x (8192 B)

    const int tid = threadIdx.x;
    const int m0 = blockIdx.x * 32;
    const int bs = m0 >> 12;
    const int n0 = m0 & (NN - 1);

    #pragma unroll
    for (int r = 0; r < 32; r++) {
        int idx = tid + 256 * r;            // idx = h*64 + c
        Wt[idx & 63][idx >> 6] = W[idx];
    }
    #pragma unroll
    for (int j = 0; j < 2; j++) {
        int q = tid + 256 * j;
        int r = q >> 4, c4 = (q & 15) * 4;
        *(float4*)(&xs[r][c4]) = *(const float4*)(x + (size_t)(m0 + r) * CC + c4);
    }
    __syncthreads();

    const int hq = tid & 31;                // h = hq*4
    const int rseg = tid >> 5;              // rows rseg*4..+3
    float acc[4][4];
    #pragma unroll
    for (int r = 0; r < 4; r++)
        #pragma unroll
        for (int j = 0; j < 4; j++) acc[r][j] = 0.f;

    #pragma unroll
    for (int c4 = 0; c4 < 16; c4++) {
        float4 w[4], xv[4];
        #pragma unroll
        for (int cc = 0; cc < 4; cc++)
            w[cc] = *(const float4*)(&Wt[c4 * 4 + cc][hq * 4]);
        #pragma unroll
        for (int r = 0; r < 4; r++)
            xv[r] = *(const float4*)(&xs[rseg * 4 + r][c4 * 4]);
        #pragma unroll
        for (int r = 0; r < 4; r++) {
            #pragma unroll
            for (int j = 0; j < 4; j++) {
                acc[r][j] += xv[r].x * ((const float*)&w[0])[j];
                acc[r][j] += xv[r].y * ((const float*)&w[1])[j];
                acc[r][j] += xv[r].z * ((const float*)&w[2])[j];
                acc[r][j] += xv[r].w * ((const float*)&w[3])[j];
            }
        }
    }

    #pragma unroll
    for (int r = 0; r < 4; r++) {
        float* orow = g_xemb + ((size_t)(m0 + rseg * 4 + r)) * HH + hq * 4;
        *(float4*)orow = make_float4(acc[r][0], acc[r][1], acc[r][2], acc[r][3]);
    }

    // e4m3(64*d_k*E) transposed -> [h][k] via smem (row stride 48 B, 16B mult)
    __syncthreads();
    uint8_t (*sht)[48] = (uint8_t(*)[48])Wt;   // [128][48] = 6144 B
    #pragma unroll
    for (int r = 0; r < 4; r++) {
        float dk = g_d[n0 + rseg * 4 + r] * SZ;
        #pragma unroll
        for (int j = 0; j < 4; j++)
            sht[hq * 4 + j][rseg * 4 + r] =
                (uint8_t)__nv_cvt_float_to_fp8(dk * acc[r][j], __NV_SATFINITE, __NV_E4M3);
    }
    __syncthreads();
    {
        int h = tid >> 1;
        int ko = (tid & 1) * 16;
        uint4 v = *(const uint4*)(&sht[h][ko]);     // 48*h + ko : 16B-aligned
        *(uint4*)(g_e8t + ((size_t)bs * HH + h) * NN + n0 + ko) = v;
    }
}

// ---------------------------------------------------------------------------
// Kernel 3: fp8 mma.sync GEMM + fused epilogue.
// 128x128 tile, BK=128 fp8, XOR-swizzled smem, 3-stage cp.async pipeline.
// 8 warps of 64x32; m16n8k32 e4m3.
// ---------------------------------------------------------------------------
#define TILE_SM 16384u                            // 128 rows x 128 B
#define STAGE_SM (2u * TILE_SM)
#define GEMM_SMEM (3u * STAGE_SM)                 // 98304 B
#define AOFF(b) ((uint32_t)(b) * STAGE_SM)
#define BOFF(b) (AOFF(b) + TILE_SM)

__device__ __forceinline__ void stage_tile(uint32_t sb,
                                           const uint8_t* __restrict__ gA,
                                           const uint8_t* __restrict__ gB,
                                           int k0, int buf, int tid) {
    #pragma unroll
    for (int j = 0; j < 4; j++) {
        int q = tid + 256 * j;               // 0..1023 chunks (16 B = 16 fp8)
        int row = q >> 3;
        int c = q & 7;
        uint32_t so = (uint32_t)(row * 128 + ((c ^ (row & 7)) * 16));
        CP_ASYNC16(sb + AOFF(buf) + so, gA + (size_t)row * NN + k0 + c * 16);
        CP_ASYNC16(sb + BOFF(buf) + so, gB + (size_t)row * NN + k0 + c * 16);
    }
}

__global__ void __launch_bounds__(256, 2) gcn_mma_kernel(float* __restrict__ out) {
    extern __shared__ __align__(128) char smem[];
    const uint32_t sb = smem_u32(smem);
    const int tid = threadIdx.x;
    const int wid = tid >> 5, lane = tid & 31;
    const int i0 = blockIdx.x * 128;
    const int bs = blockIdx.y;
    const int wm = (wid >> 2) * 64;
    const int wn = (wid & 3) * 32;

    const uint8_t* gA = g_a8 + (size_t)i0 * NN;
    const uint8_t* gB = g_e8t + (size_t)bs * HH * NN;

    float c[4][4][4];
    #pragma unroll
    for (int mt = 0; mt < 4; mt++)
        #pragma unroll
        for (int nt = 0; nt < 4; nt++)
            #pragma unroll
            for (int r = 0; r < 4; r++) c[mt][nt][r] = 0.f;

    stage_tile(sb, gA, gB, 0, 0, tid);   CP_COMMIT();
    stage_tile(sb, gA, gB, 128, 1, tid); CP_COMMIT();

    const int NS = NN / 128;             // 32 stages
    for (int s = 0; s < NS; s++) {
        if (s + 1 < NS) CP_WAIT1(); else CP_WAIT0();
        __syncthreads();
        if (s + 2 < NS) { stage_tile(sb, gA, gB, (s + 2) * 128, (s + 2) % 3, tid); CP_COMMIT(); }

        const uint32_t sA = sb + AOFF(s % 3);
        const uint32_t sB = sb + BOFF(s % 3);
        #pragma unroll
        for (int kk = 0; kk < 4; kk++) {         // k32 fp8 per iter
            uint32_t a[4][4];
            #pragma unroll
            for (int mt = 0; mt < 4; mt++) {
                int row = wm + mt * 16 + (lane & 15);
                int ch  = kk * 2 + (lane >> 4);
                LDSM_X4(a[mt], sA + (uint32_t)(row * 128 + ((ch ^ (row & 7)) * 16)));
            }
            uint32_t b[2][4];
            #pragma unroll
            for (int nh = 0; nh < 2; nh++) {
                int nrow = wn + nh * 16 + (lane & 7) + ((lane >> 4) << 3);
                int ch   = kk * 2 + ((lane >> 3) & 1);
                LDSM_X4(b[nh], sB + (uint32_t)(nrow * 128 + ((ch ^ (nrow & 7)) * 16)));
            }
            #pragma unroll
            for (int mt = 0; mt < 4; mt++)
                #pragma unroll
                for (int nt = 0; nt < 4; nt++)
                    mma_fp8(c[mt][nt], a[mt],
                            b[nt >> 1][(nt & 1) * 2], b[nt >> 1][(nt & 1) * 2 + 1]);
        }
    }

    // fused epilogue: out = sigmoid(E - (d_i/1024) * acc_q)
    #pragma unroll
    for (int mt = 0; mt < 4; mt++) {
        int r0 = i0 + wm + mt * 16 + (lane >> 2);
        int r1 = r0 + 8;
        float d0 = g_d[r0] * INV_SASZ, d1 = g_d[r1] * INV_SASZ;
        const float* e0 = g_xemb + ((size_t)bs * NN + r0) * HH;
        const float* e1 = g_xemb + ((size_t)bs * NN + r1) * HH;
        float* o0 = out + ((size_t)bs * NN + r0) * HH;
        float* o1 = out + ((size_t)bs * NN + r1) * HH;
        #pragma unroll
        for (int nt = 0; nt < 4; nt++) {
            int col = wn + nt * 8 + (lane & 3) * 2;
            float2 ea = *(const float2*)(e0 + col);
            float2 eb = *(const float2*)(e1 + col);
            float2 oa, ob;
            oa.x = 1.f / (1.f + __expf(-(ea.x - d0 * c[mt][nt][0])));
            oa.y = 1.f / (1.f + __expf(-(ea.y - d0 * c[mt][nt][1])));
            ob.x = 1.f / (1.f + __expf(-(eb.x - d1 * c[mt][nt][2])));
            ob.y = 1.f / (1.f + __expf(-(eb.y - d1 * c[mt][nt][3])));
            *(float2*)(o0 + col) = oa;
            *(float2*)(o1 + col) = ob;
        }
    }
}

// ---------------------------------------------------------------------------
extern "C" void kernel_launch(void* const* d_in, const int* in_sizes, int n_in,
                              void* d_out, int out_size) {
    const float* x = (const float*)d_in[0];
    const float* A = (const float*)d_in[1];
    const float* W = (const float*)d_in[2];
    float* out = (float*)d_out;

    cudaFuncSetAttribute(gcn_mma_kernel,
                         cudaFuncAttributeMaxDynamicSharedMemorySize, GEMM_SMEM);

    rowpass_kernel<<<NN, 256>>>(A, out + OUT_ELEMS);
    emb_kernel<<<(NBS * NN) / 32, 256>>>(x, W);
    gcn_mma_kernel<<<dim3(NN / 128, NBS), 256, GEMM_SMEM>>>(out);
}